// round 1
// baseline (speedup 1.0000x reference)
#include <cuda_runtime.h>

// ChamferDistance: B=4, N=M=8192, 3-D points.
// dist1[b,i] = min_j ||xyz1[b,i]-xyz2[b,j]||^2, idx1 = argmin (first index on ties)
// dist2/idx2 symmetric. Output (float32): [dist1 | dist2 | idx1 | idx2], each B*N.

#define BATCH 4
#define NPTS  8192
#define TPB   128          // threads per block
#define IPQ   8            // queries per thread (in registers)
#define QTILE (TPB * IPQ)  // 1024 queries per block
#define JTILE 1024         // reference points per block (j-slice)

// Scratch: packed (float_bits(best_d) << 32) | best_j per query, per direction.
// d >= 0 so float bits are monotonic; min over packed key = (min d, then min j)
// which exactly matches argmin first-index tie-breaking.
__device__ unsigned long long g_best[2][BATCH * NPTS];

__global__ void init_best_kernel() {
    int i = blockIdx.x * blockDim.x + threadIdx.x;
    if (i < 2 * BATCH * NPTS)
        (&g_best[0][0])[i] = 0xFFFFFFFFFFFFFFFFull;
}

__global__ void __launch_bounds__(TPB)
chamfer_dir_kernel(const float* __restrict__ q,   // [B, NPTS, 3] query side
                   const float* __restrict__ r,   // [B, NPTS, 3] reference side
                   int dir)                       // 0: xyz1->xyz2, 1: xyz2->xyz1
{
    __shared__ float sx[JTILE], sy[JTILE], sz[JTILE];

    const int b     = blockIdx.z;
    const int qbase = blockIdx.x * QTILE;
    const int j0    = blockIdx.y * JTILE;
    const int t     = threadIdx.x;

    // Stage reference slice into shared, SoA for broadcast LDS.
    for (int idx = t; idx < JTILE; idx += TPB) {
        const float* p = r + ((size_t)b * NPTS + j0 + idx) * 3;
        sx[idx] = p[0];
        sy[idx] = p[1];
        sz[idx] = p[2];
    }
    __syncthreads();

    // Load 8 query points into registers (stride-TPB for coalescing).
    float qx[IPQ], qy[IPQ], qz[IPQ], bd[IPQ];
    int bj[IPQ];
#pragma unroll
    for (int k = 0; k < IPQ; k++) {
        const int qi = qbase + t + k * TPB;
        const float* p = q + ((size_t)b * NPTS + qi) * 3;
        qx[k] = p[0];
        qy[k] = p[1];
        qz[k] = p[2];
        bd[k] = 3.4028235e38f;
        bj[k] = 0;
    }

    // Brute-force scan of the j-slice. Arithmetic order matches the reference:
    // ((dx*dx + dy*dy) + dz*dz), no FMA contraction, so near-tie argmins agree.
#pragma unroll 4
    for (int jj = 0; jj < JTILE; ++jj) {
        const float rx = sx[jj], ry = sy[jj], rz = sz[jj];
#pragma unroll
        for (int k = 0; k < IPQ; k++) {
            const float dx = qx[k] - rx;
            const float dy = qy[k] - ry;
            const float dz = qz[k] - rz;
            const float d = __fadd_rn(__fadd_rn(__fmul_rn(dx, dx),
                                                __fmul_rn(dy, dy)),
                                      __fmul_rn(dz, dz));
            if (d < bd[k]) {   // strict <: keeps first (lowest) j within the scan
                bd[k] = d;
                bj[k] = j0 + jj;
            }
        }
    }

    // Merge partials across j-slices.
    unsigned long long* best = &g_best[dir][0];
#pragma unroll
    for (int k = 0; k < IPQ; k++) {
        const int qi = qbase + t + k * TPB;
        const unsigned long long key =
            ((unsigned long long)__float_as_uint(bd[k]) << 32) | (unsigned)bj[k];
        atomicMin(&best[(size_t)b * NPTS + qi], key);
    }
}

__global__ void pack_out_kernel(float* __restrict__ out) {
    const int i = blockIdx.x * blockDim.x + threadIdx.x;
    const int n = BATCH * NPTS;
    if (i >= n) return;
    const unsigned long long k1 = g_best[0][i];
    const unsigned long long k2 = g_best[1][i];
    out[i]         = __uint_as_float((unsigned)(k1 >> 32));        // dist1
    out[n + i]     = __uint_as_float((unsigned)(k2 >> 32));        // dist2
    out[2 * n + i] = (float)(unsigned)(k1 & 0xFFFFFFFFu);          // idx1
    out[3 * n + i] = (float)(unsigned)(k2 & 0xFFFFFFFFu);          // idx2
}

extern "C" void kernel_launch(void* const* d_in, const int* in_sizes, int n_in,
                              void* d_out, int out_size) {
    const float* xyz1 = (const float*)d_in[0];
    const float* xyz2 = (const float*)d_in[1];
    float* out = (float*)d_out;

    init_best_kernel<<<(2 * BATCH * NPTS + 255) / 256, 256>>>();

    dim3 grid(NPTS / QTILE, NPTS / JTILE, BATCH);  // (8, 8, 4) = 256 blocks/dir
    chamfer_dir_kernel<<<grid, TPB>>>(xyz1, xyz2, 0);  // dist1/idx1
    chamfer_dir_kernel<<<grid, TPB>>>(xyz2, xyz1, 1);  // dist2/idx2

    pack_out_kernel<<<(BATCH * NPTS + 255) / 256, 256>>>(out);
}

// round 2
// speedup vs baseline: 1.5389x; 1.5389x over previous
#include <cuda_runtime.h>

// ChamferDistance: B=4, N=M=8192, 3-D points.
// Output (float32): [dist1 | dist2 | idx1 | idx2], each B*N.
//
// Strategy: issue-bound brute force. Packed f32x2 math (2 fp32 rn ops per
// issue slot, bit-identical per lane to scalar) computes distances for two
// query points at once. References staged in smem negated+duplicated so a
// single broadcast LDS.64 feeds add.rn.f32x2 (sub == add of neg, exact).
// Cross-block merge via 64-bit atomicMin on (d_bits<<32)|j -> min d, then
// min j on ties == jnp.argmin first-index semantics.

#define BATCH 4
#define NPTS  8192
#define TPB   128
#define IPQ   8             // queries per thread (4 packed pairs)
#define QTILE (TPB * IPQ)   // 1024 queries per block
#define JTILE 1024          // reference slice per block

typedef unsigned long long u64;

__device__ u64 g_best[2][BATCH * NPTS];

__device__ __forceinline__ u64 f2_add(u64 a, u64 b) {
    u64 r; asm("add.rn.f32x2 %0, %1, %2;" : "=l"(r) : "l"(a), "l"(b)); return r;
}
__device__ __forceinline__ u64 f2_mul(u64 a, u64 b) {
    u64 r; asm("mul.rn.f32x2 %0, %1, %2;" : "=l"(r) : "l"(a), "l"(b)); return r;
}
__device__ __forceinline__ u64 f2_pack(float lo, float hi) {
    u64 r; asm("mov.b64 %0, {%1, %2};" : "=l"(r) : "f"(lo), "f"(hi)); return r;
}
__device__ __forceinline__ void f2_unpack(float& lo, float& hi, u64 v) {
    asm("mov.b64 {%0, %1}, %2;" : "=f"(lo), "=f"(hi) : "l"(v));
}

__global__ void init_best_kernel() {
    int i = blockIdx.x * blockDim.x + threadIdx.x;
    if (i < 2 * BATCH * NPTS)
        (&g_best[0][0])[i] = 0xFFFFFFFFFFFFFFFFull;
}

__global__ void __launch_bounds__(TPB)
chamfer_kernel(const float* __restrict__ xyz1, const float* __restrict__ xyz2)
{
    // Packed (-x,-x), (-y,-y), (-z,-z) per reference point: broadcast LDS.64.
    __shared__ u64 snx[JTILE], sny[JTILE], snz[JTILE];

    const int zc    = blockIdx.z;          // 0..7 : dir = zc>>2, b = zc&3
    const int dir   = zc >> 2;
    const int b     = zc & 3;
    const float* q  = dir ? xyz2 : xyz1;
    const float* r  = dir ? xyz1 : xyz2;

    const int qbase = blockIdx.x * QTILE;
    const int j0    = blockIdx.y * JTILE;
    const int t     = threadIdx.x;

    // Stage reference slice: negate + duplicate into 8B packed entries.
    for (int idx = t; idx < JTILE; idx += TPB) {
        const float* p = r + ((size_t)b * NPTS + j0 + idx) * 3;
        float nx = -p[0], ny = -p[1], nz = -p[2];
        snx[idx] = f2_pack(nx, nx);
        sny[idx] = f2_pack(ny, ny);
        snz[idx] = f2_pack(nz, nz);
    }
    __syncthreads();

    // Load 8 query points (stride-TPB, coalesced), pack into 4 f32x2 pairs.
    // Pair p covers query slots (2p, 2p+1) -> qi = qbase + t + k*TPB.
    float qx[IPQ], qy[IPQ], qz[IPQ], bd[IPQ];
    int bj[IPQ];
#pragma unroll
    for (int k = 0; k < IPQ; k++) {
        const float* p = q + ((size_t)b * NPTS + qbase + t + k * TPB) * 3;
        qx[k] = p[0]; qy[k] = p[1]; qz[k] = p[2];
        bd[k] = 3.4028235e38f;
        bj[k] = 0;
    }
    u64 qx2[IPQ / 2], qy2[IPQ / 2], qz2[IPQ / 2];
#pragma unroll
    for (int p = 0; p < IPQ / 2; p++) {
        qx2[p] = f2_pack(qx[2 * p], qx[2 * p + 1]);
        qy2[p] = f2_pack(qy[2 * p], qy[2 * p + 1]);
        qz2[p] = f2_pack(qz[2 * p], qz[2 * p + 1]);
    }

    // Main scan. Per-lane arithmetic identical to reference order:
    // d = ((dx*dx + dy*dy) + dz*dz), all rn, no FMA contraction.
#pragma unroll 2
    for (int jj = 0; jj < JTILE; ++jj) {
        const u64 nrx = snx[jj], nry = sny[jj], nrz = snz[jj];
        const int j = j0 + jj;
#pragma unroll
        for (int p = 0; p < IPQ / 2; p++) {
            u64 dx = f2_add(qx2[p], nrx);
            u64 dy = f2_add(qy2[p], nry);
            u64 dz = f2_add(qz2[p], nrz);
            u64 d2 = f2_add(f2_add(f2_mul(dx, dx), f2_mul(dy, dy)),
                            f2_mul(dz, dz));
            float dlo, dhi;
            f2_unpack(dlo, dhi, d2);
            if (dlo < bd[2 * p])     { bd[2 * p]     = dlo; bj[2 * p]     = j; }
            if (dhi < bd[2 * p + 1]) { bd[2 * p + 1] = dhi; bj[2 * p + 1] = j; }
        }
    }

    // Merge partial mins across j-slices.
    u64* best = &g_best[dir][0];
#pragma unroll
    for (int k = 0; k < IPQ; k++) {
        const int qi = qbase + t + k * TPB;
        const u64 key = ((u64)__float_as_uint(bd[k]) << 32) | (unsigned)bj[k];
        atomicMin(&best[(size_t)b * NPTS + qi], key);
    }
}

__global__ void pack_out_kernel(float* __restrict__ out) {
    const int i = blockIdx.x * blockDim.x + threadIdx.x;
    const int n = BATCH * NPTS;
    if (i >= n) return;
    const u64 k1 = g_best[0][i];
    const u64 k2 = g_best[1][i];
    out[i]         = __uint_as_float((unsigned)(k1 >> 32));   // dist1
    out[n + i]     = __uint_as_float((unsigned)(k2 >> 32));   // dist2
    out[2 * n + i] = (float)(unsigned)(k1 & 0xFFFFFFFFu);     // idx1
    out[3 * n + i] = (float)(unsigned)(k2 & 0xFFFFFFFFu);     // idx2
}

extern "C" void kernel_launch(void* const* d_in, const int* in_sizes, int n_in,
                              void* d_out, int out_size) {
    const float* xyz1 = (const float*)d_in[0];
    const float* xyz2 = (const float*)d_in[1];
    float* out = (float*)d_out;

    init_best_kernel<<<(2 * BATCH * NPTS + 255) / 256, 256>>>();

    dim3 grid(NPTS / QTILE, NPTS / JTILE, BATCH * 2);  // (8, 8, 8) = 512 blocks
    chamfer_kernel<<<grid, TPB>>>(xyz1, xyz2);

    pack_out_kernel<<<(BATCH * NPTS + 255) / 256, 256>>>(out);
}

// round 5
// speedup vs baseline: 1.6375x; 1.0641x over previous
#include <cuda_runtime.h>

// ChamferDistance: B=4, N=M=8192, 3-D points.
// Output (float32): [dist1 | dist2 | idx1 | idx2], each B*N.
//
// Issue-bound brute force at the exact-arithmetic instruction floor:
//   per pair-eval: 4 packed-f32x2 issues (8 fp ops) + 3 cmp/sel.
// This round: IPQ 8->4 doubles resident warps (6.9/SMSP) so the fma pipe
// (rt 2, the binding resource) stays fed; all 1024 blocks co-resident.
// Per-lane arithmetic is bit-identical to the reference (((dx^2+dy^2)+dz^2),
// rn, no FMA) so distances AND argmin tie-breaks match exactly.

#define BATCH 4
#define NPTS  8192
#define TPB   128
#define IPQ   4             // queries per thread (2 packed pairs)
#define QTILE (TPB * IPQ)   // 512 queries per block
#define JTILE 1024          // reference slice per block

typedef unsigned long long u64;

__device__ u64 g_best[2][BATCH * NPTS];

__device__ __forceinline__ u64 f2_add(u64 a, u64 b) {
    u64 r; asm("add.rn.f32x2 %0, %1, %2;" : "=l"(r) : "l"(a), "l"(b)); return r;
}
__device__ __forceinline__ u64 f2_mul(u64 a, u64 b) {
    u64 r; asm("mul.rn.f32x2 %0, %1, %2;" : "=l"(r) : "l"(a), "l"(b)); return r;
}
__device__ __forceinline__ u64 f2_pack(float lo, float hi) {
    u64 r; asm("mov.b64 %0, {%1, %2};" : "=l"(r) : "f"(lo), "f"(hi)); return r;
}
__device__ __forceinline__ void f2_unpack(float& lo, float& hi, u64 v) {
    asm("mov.b64 {%0, %1}, %2;" : "=f"(lo), "=f"(hi) : "l"(v));
}

__global__ void init_best_kernel() {
    int i = blockIdx.x * blockDim.x + threadIdx.x;
    if (i < 2 * BATCH * NPTS)
        (&g_best[0][0])[i] = 0xFFFFFFFFFFFFFFFFull;
}

__global__ void __launch_bounds__(TPB)
chamfer_kernel(const float* __restrict__ xyz1, const float* __restrict__ xyz2)
{
    // Packed (-x,-x), (-y,-y), (-z,-z) per reference point: broadcast LDS.64,
    // and sub == add of negated (exact).
    __shared__ u64 snx[JTILE], sny[JTILE], snz[JTILE];

    const int zc    = blockIdx.z;          // dir = zc>>2, b = zc&3
    const int dir   = zc >> 2;
    const int b     = zc & 3;
    const float* q  = dir ? xyz2 : xyz1;
    const float* r  = dir ? xyz1 : xyz2;

    const int qbase = blockIdx.x * QTILE;
    const int j0    = blockIdx.y * JTILE;
    const int t     = threadIdx.x;

    for (int idx = t; idx < JTILE; idx += TPB) {
        const float* p = r + ((size_t)b * NPTS + j0 + idx) * 3;
        float nx = -p[0], ny = -p[1], nz = -p[2];
        snx[idx] = f2_pack(nx, nx);
        sny[idx] = f2_pack(ny, ny);
        snz[idx] = f2_pack(nz, nz);
    }
    __syncthreads();

    // 4 query points per thread (stride-TPB), packed into 2 f32x2 pairs.
    float bd[IPQ];
    int bj[IPQ];
    u64 qx2[IPQ / 2], qy2[IPQ / 2], qz2[IPQ / 2];
#pragma unroll
    for (int p = 0; p < IPQ / 2; p++) {
        const float* p0 = q + ((size_t)b * NPTS + qbase + t + (2 * p) * TPB) * 3;
        const float* p1 = q + ((size_t)b * NPTS + qbase + t + (2 * p + 1) * TPB) * 3;
        qx2[p] = f2_pack(p0[0], p1[0]);
        qy2[p] = f2_pack(p0[1], p1[1]);
        qz2[p] = f2_pack(p0[2], p1[2]);
    }
#pragma unroll
    for (int k = 0; k < IPQ; k++) { bd[k] = 3.4028235e38f; bj[k] = 0; }

    // Main scan: per-lane d = ((dx*dx + dy*dy) + dz*dz), all rn, no FMA.
#pragma unroll 4
    for (int jj = 0; jj < JTILE; ++jj) {
        const u64 nrx = snx[jj], nry = sny[jj], nrz = snz[jj];
        const int j = j0 + jj;
#pragma unroll
        for (int p = 0; p < IPQ / 2; p++) {
            u64 dx = f2_add(qx2[p], nrx);
            u64 dy = f2_add(qy2[p], nry);
            u64 dz = f2_add(qz2[p], nrz);
            u64 d2 = f2_add(f2_add(f2_mul(dx, dx), f2_mul(dy, dy)),
                            f2_mul(dz, dz));
            float dlo, dhi;
            f2_unpack(dlo, dhi, d2);
            if (dlo < bd[2 * p])     { bd[2 * p]     = dlo; bj[2 * p]     = j; }
            if (dhi < bd[2 * p + 1]) { bd[2 * p + 1] = dhi; bj[2 * p + 1] = j; }
        }
    }

    // Merge partial mins across j-slices: min over (d_bits<<32)|j gives
    // min d with lowest-j tie-break == jnp.argmin first-index semantics.
    u64* best = &g_best[dir][0];
#pragma unroll
    for (int k = 0; k < IPQ; k++) {
        const int qi = qbase + t + k * TPB;
        const u64 key = ((u64)__float_as_uint(bd[k]) << 32) | (unsigned)bj[k];
        atomicMin(&best[(size_t)b * NPTS + qi], key);
    }
}

__global__ void pack_out_kernel(float* __restrict__ out) {
    const int i = blockIdx.x * blockDim.x + threadIdx.x;
    const int n = BATCH * NPTS;
    if (i >= n) return;
    const u64 k1 = g_best[0][i];
    const u64 k2 = g_best[1][i];
    out[i]         = __uint_as_float((unsigned)(k1 >> 32));   // dist1
    out[n + i]     = __uint_as_float((unsigned)(k2 >> 32));   // dist2
    out[2 * n + i] = (float)(unsigned)(k1 & 0xFFFFFFFFu);     // idx1
    out[3 * n + i] = (float)(unsigned)(k2 & 0xFFFFFFFFu);     // idx2
}

extern "C" void kernel_launch(void* const* d_in, const int* in_sizes, int n_in,
                              void* d_out, int out_size) {
    const float* xyz1 = (const float*)d_in[0];
    const float* xyz2 = (const float*)d_in[1];
    float* out = (float*)d_out;

    init_best_kernel<<<(2 * BATCH * NPTS + 255) / 256, 256>>>();

    dim3 grid(NPTS / QTILE, NPTS / JTILE, BATCH * 2);  // (16, 8, 8) = 1024 blocks
    chamfer_kernel<<<grid, TPB>>>(xyz1, xyz2);

    pack_out_kernel<<<(BATCH * NPTS + 255) / 256, 256>>>(out);
}

// round 6
// speedup vs baseline: 1.7914x; 1.0940x over previous
#include <cuda_runtime.h>

// ChamferDistance: B=4, N=M=8192, 3-D points.
// Output (float32): [dist1 | dist2 | idx1 | idx2], each B*N.
//
// Bit-exact brute force at the fma-pipe floor. Packed f32x2 math (rn, no FMA,
// per-lane identical to reference ((dx^2+dy^2)+dz^2)) -> distances AND argmin
// tie-breaks match exactly. Refs staged in smem negated+duplicated, paired so
// one LDS.128 feeds two j iterations. Per-slice partial (d_bits<<32|j) keys
// written with plain stores (no init kernel, no atomics); final 8-way min in
// the pack kernel. u64 key min == (min d, then lowest j) == jnp.argmin.

#define BATCH 4
#define NPTS  8192
#define TPB   128
#define IPQ   4             // queries per thread (2 packed pairs)
#define QTILE (TPB * IPQ)   // 512 queries per block
#define JTILE 1024          // reference slice per block
#define NSLICE (NPTS / JTILE)   // 8

typedef unsigned long long u64;

// Per-slice partials: [dir][b][slice][query]  (4 MB, fully overwritten each launch)
__device__ u64 g_part[2 * BATCH * NSLICE * NPTS];

__device__ __forceinline__ u64 f2_add(u64 a, u64 b) {
    u64 r; asm("add.rn.f32x2 %0, %1, %2;" : "=l"(r) : "l"(a), "l"(b)); return r;
}
__device__ __forceinline__ u64 f2_mul(u64 a, u64 b) {
    u64 r; asm("mul.rn.f32x2 %0, %1, %2;" : "=l"(r) : "l"(a), "l"(b)); return r;
}
__device__ __forceinline__ u64 f2_pack(float lo, float hi) {
    u64 r; asm("mov.b64 %0, {%1, %2};" : "=l"(r) : "f"(lo), "f"(hi)); return r;
}
__device__ __forceinline__ void f2_unpack(float& lo, float& hi, u64 v) {
    asm("mov.b64 {%0, %1}, %2;" : "=f"(lo), "=f"(hi) : "l"(v));
}

__global__ void __launch_bounds__(TPB)
chamfer_kernel(const float* __restrict__ xyz1, const float* __restrict__ xyz2)
{
    // Pair-interleaved refs: sref[p] = {nx_j,nx_j1, ny_j,ny_j1, nz_j,nz_j1},
    // each entry an f32x2-duplicated negated component. 48B per pair; every
    // component pair is 16B-aligned -> LDS.128 broadcast.
    __shared__ __align__(16) u64 sref[JTILE / 2][6];

    const int zc    = blockIdx.z;          // dir = zc>>2, b = zc&3
    const int dir   = zc >> 2;
    const int b     = zc & 3;
    const float* q  = dir ? xyz2 : xyz1;
    const float* r  = dir ? xyz1 : xyz2;

    const int qbase = blockIdx.x * QTILE;
    const int slice = blockIdx.y;
    const int j0    = slice * JTILE;
    const int t     = threadIdx.x;

    for (int idx = t; idx < JTILE; idx += TPB) {
        const float* p = r + ((size_t)b * NPTS + j0 + idx) * 3;
        float nx = -p[0], ny = -p[1], nz = -p[2];
        sref[idx >> 1][0 + (idx & 1)] = f2_pack(nx, nx);
        sref[idx >> 1][2 + (idx & 1)] = f2_pack(ny, ny);
        sref[idx >> 1][4 + (idx & 1)] = f2_pack(nz, nz);
    }
    __syncthreads();

    // 4 query points per thread (stride-TPB), packed into 2 f32x2 pairs.
    float bd[IPQ];
    int bj[IPQ];
    u64 qx2[IPQ / 2], qy2[IPQ / 2], qz2[IPQ / 2];
#pragma unroll
    for (int p = 0; p < IPQ / 2; p++) {
        const float* p0 = q + ((size_t)b * NPTS + qbase + t + (2 * p) * TPB) * 3;
        const float* p1 = q + ((size_t)b * NPTS + qbase + t + (2 * p + 1) * TPB) * 3;
        qx2[p] = f2_pack(p0[0], p1[0]);
        qy2[p] = f2_pack(p0[1], p1[1]);
        qz2[p] = f2_pack(p0[2], p1[2]);
    }
#pragma unroll
    for (int k = 0; k < IPQ; k++) { bd[k] = 3.4028235e38f; bj[k] = 0; }

    // Main scan, 2 refs per iteration via LDS.128. Per-lane arithmetic:
    // d = ((dx*dx + dy*dy) + dz*dz), all rn, no FMA -> bit-exact vs reference.
#pragma unroll 2
    for (int pp = 0; pp < JTILE / 2; ++pp) {
        const ulonglong2 vx = *reinterpret_cast<const ulonglong2*>(&sref[pp][0]);
        const ulonglong2 vy = *reinterpret_cast<const ulonglong2*>(&sref[pp][2]);
        const ulonglong2 vz = *reinterpret_cast<const ulonglong2*>(&sref[pp][4]);
        const int jj = 2 * pp;
#pragma unroll
        for (int h = 0; h < 2; h++) {
            const u64 nrx = h ? vx.y : vx.x;
            const u64 nry = h ? vy.y : vy.x;
            const u64 nrz = h ? vz.y : vz.x;
            const int j = jj + h;   // slice-local index; j0 added at the end
#pragma unroll
            for (int p = 0; p < IPQ / 2; p++) {
                u64 dx = f2_add(qx2[p], nrx);
                u64 dy = f2_add(qy2[p], nry);
                u64 dz = f2_add(qz2[p], nrz);
                u64 d2 = f2_add(f2_add(f2_mul(dx, dx), f2_mul(dy, dy)),
                                f2_mul(dz, dz));
                float dlo, dhi;
                f2_unpack(dlo, dhi, d2);
                if (dlo < bd[2 * p])     { bd[2 * p]     = dlo; bj[2 * p]     = j; }
                if (dhi < bd[2 * p + 1]) { bd[2 * p + 1] = dhi; bj[2 * p + 1] = j; }
            }
        }
    }

    // Plain store of this slice's partial key.
    u64* part = g_part + (((size_t)(dir * BATCH + b) * NSLICE + slice) * NPTS);
#pragma unroll
    for (int k = 0; k < IPQ; k++) {
        const int qi = qbase + t + k * TPB;
        part[qi] = ((u64)__float_as_uint(bd[k]) << 32) | (unsigned)(j0 + bj[k]);
    }
}

__global__ void pack_out_kernel(float* __restrict__ out) {
    const int i = blockIdx.x * blockDim.x + threadIdx.x;   // (dir,b,q)
    if (i >= 2 * BATCH * NPTS) return;
    const int dir = i / (BATCH * NPTS);
    const int bq  = i - dir * (BATCH * NPTS);              // b*NPTS + q

    const u64* part = g_part + ((size_t)dir * BATCH * NSLICE * NPTS);
    const int b = bq / NPTS, qq = bq - b * NPTS;
    u64 best = 0xFFFFFFFFFFFFFFFFull;
#pragma unroll
    for (int s = 0; s < NSLICE; s++) {
        u64 k = part[((size_t)(b * NSLICE + s)) * NPTS + qq];
        best = (k < best) ? k : best;
    }
    const int n = BATCH * NPTS;
    out[dir * n + bq]       = __uint_as_float((unsigned)(best >> 32));  // dist
    out[(2 + dir) * n + bq] = (float)(unsigned)(best & 0xFFFFFFFFu);    // idx
}

extern "C" void kernel_launch(void* const* d_in, const int* in_sizes, int n_in,
                              void* d_out, int out_size) {
    const float* xyz1 = (const float*)d_in[0];
    const float* xyz2 = (const float*)d_in[1];
    float* out = (float*)d_out;

    dim3 grid(NPTS / QTILE, NSLICE, BATCH * 2);  // (16, 8, 8) = 1024 blocks
    chamfer_kernel<<<grid, TPB>>>(xyz1, xyz2);

    pack_out_kernel<<<(2 * BATCH * NPTS + 255) / 256, 256>>>(out);
}